// round 3
// baseline (speedup 1.0000x reference)
#include <cuda_runtime.h>
#include <cuda_bf16.h>
#include <cstdint>

static constexpr int NB = 16, NN = 2048, DD = 64;
static constexpr int BM = 128, BN = 128, NKT = NN / BN, TB = 256;

// SMEM: six bf16 [128 x 64] panels (128B rows, XOR-swizzled), 16KB each
static constexpr int SM_QH = 0, SM_QL = 16384, SM_KH = 32768, SM_KL = 49152,
                     SM_VH = 65536, SM_VL = 81920;
static constexpr int SMEM_TOTAL = 98304;

__device__ __forceinline__ uint32_t smem_u32(const void* p) {
    uint32_t a;
    asm("{ .reg .u64 t; cvta.to.shared.u64 t, %1; cvt.u32.u64 %0, t; }" : "=r"(a) : "l"(p));
    return a;
}
__device__ __forceinline__ uint32_t sw128(uint32_t bo) { return bo ^ ((bo >> 3) & 0x70); }
__device__ __forceinline__ float ex2f(float x) {
    float y; asm("ex2.approx.f32 %0, %1;" : "=f"(y) : "f"(x)); return y;
}
__device__ __forceinline__ uint32_t bfpack(__nv_bfloat16 a, __nv_bfloat16 b) {
    uint16_t x, y;
    x = *reinterpret_cast<uint16_t*>(&a); y = *reinterpret_cast<uint16_t*>(&b);
    return (uint32_t)x | ((uint32_t)y << 16);
}
__device__ __forceinline__ void split1(float f, __nv_bfloat16& h, __nv_bfloat16& l) {
    h = __float2bfloat16(f);
    l = __float2bfloat16(f - __bfloat162float(h));
}
// store fp32x4 at (row, col..col+3) into hi & lo bf16 panels (SW128)
__device__ __forceinline__ void store_split64(char* smem, int offH, int offL,
                                              int row, int col, float4 f) {
    __nv_bfloat16 h0,h1,h2,h3,l0,l1,l2,l3;
    split1(f.x,h0,l0); split1(f.y,h1,l1); split1(f.z,h2,l2); split1(f.w,h3,l3);
    uint32_t bo = (uint32_t)(row * 128 + col * 2);
    uint32_t s0 = sw128(bo), s1 = sw128(bo + 4);
    *(uint32_t*)(smem + offH + s0) = bfpack(h0, h1);
    *(uint32_t*)(smem + offH + s1) = bfpack(h2, h3);
    *(uint32_t*)(smem + offL + s0) = bfpack(l0, l1);
    *(uint32_t*)(smem + offL + s1) = bfpack(l2, l3);
}

#define LDSM4(r0,r1,r2,r3,ad) \
    asm volatile("ldmatrix.sync.aligned.m8n8.x4.shared.b16 {%0,%1,%2,%3}, [%4];" \
        : "=r"(r0), "=r"(r1), "=r"(r2), "=r"(r3) : "r"(ad))
#define LDSM4T(r0,r1,r2,r3,ad) \
    asm volatile("ldmatrix.sync.aligned.m8n8.x4.trans.shared.b16 {%0,%1,%2,%3}, [%4];" \
        : "=r"(r0), "=r"(r1), "=r"(r2), "=r"(r3) : "r"(ad))

__device__ __forceinline__ void mma16816(float* c, const uint32_t* a, const uint32_t* b) {
    asm volatile("mma.sync.aligned.m16n8k16.row.col.f32.bf16.bf16.f32 "
        "{%0,%1,%2,%3}, {%4,%5,%6,%7}, {%8,%9}, {%0,%1,%2,%3};"
        : "+f"(c[0]), "+f"(c[1]), "+f"(c[2]), "+f"(c[3])
        : "r"(a[0]), "r"(a[1]), "r"(a[2]), "r"(a[3]), "r"(b[0]), "r"(b[1]));
}

// A-frag m16k16: rows row0..row0+15, k elements kbyte/2..+15
__device__ __forceinline__ void lda_frag(uint32_t* fr, uint32_t tile, int row0, int kbyte) {
    int lane = threadIdx.x & 31;
    int r = row0 + (lane & 7) + (lane & 8);
    int cb = kbyte + ((lane & 16) ? 16 : 0);
    uint32_t ad = tile + sw128((uint32_t)(r * 128 + cb));
    LDSM4(fr[0], fr[1], fr[2], fr[3], ad);
}
// B-frags (2 n-blocks) from K-layout [n][k]: r0,r1 = nb, r2,r3 = nb+1
__device__ __forceinline__ void ldb_k(uint32_t* fr, uint32_t tile, int n0, int kbyte) {
    int lane = threadIdx.x & 31;
    int r = n0 + (lane & 7) + ((lane & 16) ? 8 : 0);
    int cb = kbyte + ((lane & 8) ? 16 : 0);
    uint32_t ad = tile + sw128((uint32_t)(r * 128 + cb));
    LDSM4(fr[0], fr[1], fr[2], fr[3], ad);
}
// B-frags (2 d-blocks) from V-layout [k][d] via trans: r0,r1 = db, r2,r3 = db+1
__device__ __forceinline__ void ldb_v(uint32_t* fr, uint32_t tile, int k0, int dbyte) {
    int lane = threadIdx.x & 31;
    int r = k0 + (lane & 7) + (lane & 8);
    int cb = dbyte + ((lane & 16) ? 16 : 0);
    uint32_t ad = tile + sw128((uint32_t)(r * 128 + cb));
    LDSM4T(fr[0], fr[1], fr[2], fr[3], ad);
}

// S = Q K^T (128x128) with 3-product bf16 split; per-warp rows [wrow0, wrow0+16)
__device__ __forceinline__ void qk_tile(float* sacc, uint32_t sb, int wrow0) {
    #pragma unroll
    for (int ks = 0; ks < 4; ks++) {
        uint32_t aH[4], aL[4];
        lda_frag(aH, sb + SM_QH, wrow0, ks * 32);
        lda_frag(aL, sb + SM_QL, wrow0, ks * 32);
        #pragma unroll
        for (int nb2 = 0; nb2 < 8; nb2++) {
            uint32_t bH[4], bL[4];
            ldb_k(bH, sb + SM_KH, nb2 * 16, ks * 32);
            ldb_k(bL, sb + SM_KL, nb2 * 16, ks * 32);
            float* c0 = sacc + nb2 * 8;
            mma16816(c0,     aH, bH);     mma16816(c0 + 4, aH, bH + 2);
            mma16816(c0,     aL, bH);     mma16816(c0 + 4, aL, bH + 2);
            mma16816(c0,     aH, bL);     mma16816(c0 + 4, aH, bL + 2);
        }
    }
}

__global__ void __launch_bounds__(TB, 1)
attn_kernel(const float* __restrict__ q, const float* __restrict__ k,
            const float* __restrict__ v, const float* __restrict__ scp,
            float* __restrict__ ctx, float* __restrict__ att)
{
    extern __shared__ char smem[];
    const uint32_t sb = smem_u32(smem);
    const int tid = threadIdx.x, lane = tid & 31, wid = tid >> 5;
    const int wrow0 = wid * 16;
    const int gr = lane >> 2, c2 = (lane & 3) * 2;
    const int b = blockIdx.y, q0 = blockIdx.x * BM;
    const float cexp = scp[0] * 1.4426950408889634f;

    // ---- load Q tile (persistent across both passes) ----
    {
        const float* qp = q + ((size_t)b * NN + q0) * DD;
        #pragma unroll
        for (int e = tid; e < BM * 16; e += TB) {
            int row = e >> 4, c4 = (e & 15) << 2;
            store_split64(smem, SM_QH, SM_QL, row, c4, *(const float4*)(qp + row * DD + c4));
        }
    }

    float rs0 = 0.f, rs1 = 0.f;

    // ================= pass 1: row sums =================
    for (int kt = 0; kt < NKT; kt++) {
        __syncthreads();
        const float* kp = k + ((size_t)b * NN + kt * BN) * DD;
        #pragma unroll
        for (int e = tid; e < BN * 16; e += TB) {
            int row = e >> 4, c4 = (e & 15) << 2;
            store_split64(smem, SM_KH, SM_KL, row, c4, *(const float4*)(kp + row * DD + c4));
        }
        __syncthreads();
        float sacc[64];
        #pragma unroll
        for (int i = 0; i < 64; i++) sacc[i] = 0.f;
        qk_tile(sacc, sb, wrow0);
        #pragma unroll
        for (int nb = 0; nb < 16; nb++) {
            rs0 += ex2f(sacc[nb*4+0] * cexp) + ex2f(sacc[nb*4+1] * cexp);
            rs1 += ex2f(sacc[nb*4+2] * cexp) + ex2f(sacc[nb*4+3] * cexp);
        }
    }
    rs0 += __shfl_xor_sync(0xffffffff, rs0, 1);
    rs0 += __shfl_xor_sync(0xffffffff, rs0, 2);
    rs1 += __shfl_xor_sync(0xffffffff, rs1, 1);
    rs1 += __shfl_xor_sync(0xffffffff, rs1, 2);
    const float li0 = 1.0f / rs0, li1 = 1.0f / rs1;

    // ================= pass 2: attention + O =================
    float oacc[32];
    #pragma unroll
    for (int i = 0; i < 32; i++) oacc[i] = 0.f;

    for (int kt = 0; kt < NKT; kt++) {
        __syncthreads();
        const float* kp = k + ((size_t)b * NN + kt * BN) * DD;
        const float* vp = v + ((size_t)b * NN + kt * BN) * DD;
        #pragma unroll
        for (int e = tid; e < BN * 16; e += TB) {
            int row = e >> 4, c4 = (e & 15) << 2;
            store_split64(smem, SM_KH, SM_KL, row, c4, *(const float4*)(kp + row * DD + c4));
            store_split64(smem, SM_VH, SM_VL, row, c4, *(const float4*)(vp + row * DD + c4));
        }
        __syncthreads();

        float sacc[64];
        #pragma unroll
        for (int i = 0; i < 64; i++) sacc[i] = 0.f;
        qk_tile(sacc, sb, wrow0);

        // exp, normalize, write attention, pack P into a-frags (hi/lo)
        uint32_t ph[32], pl[32];
        {
            float* arow0 = att + ((size_t)b * NN + q0 + wrow0 + gr) * NN + kt * BN + c2;
            float* arow1 = arow0 + (size_t)8 * NN;
            #pragma unroll
            for (int nb = 0; nb < 16; nb++) {
                float p0 = ex2f(sacc[nb*4+0] * cexp) * li0;
                float p1 = ex2f(sacc[nb*4+1] * cexp) * li0;
                float p2 = ex2f(sacc[nb*4+2] * cexp) * li1;
                float p3 = ex2f(sacc[nb*4+3] * cexp) * li1;
                *(float2*)(arow0 + nb * 8) = make_float2(p0, p1);
                *(float2*)(arow1 + nb * 8) = make_float2(p2, p3);
                __nv_bfloat16 h0,h1,h2,h3,l0,l1,l2,l3;
                split1(p0,h0,l0); split1(p1,h1,l1); split1(p2,h2,l2); split1(p3,h3,l3);
                int ks = nb >> 1, hf2 = (nb & 1) * 2;
                ph[ks*4 + hf2 + 0] = bfpack(h0, h1);
                ph[ks*4 + hf2 + 1] = bfpack(h2, h3);
                pl[ks*4 + hf2 + 0] = bfpack(l0, l1);
                pl[ks*4 + hf2 + 1] = bfpack(l2, l3);
            }
        }

        // O += P V  (3-product split: PhVh + PlVh + PhVl)
        #pragma unroll
        for (int ks = 0; ks < 8; ks++) {
            const uint32_t* aH = ph + ks * 4;
            const uint32_t* aL = pl + ks * 4;
            #pragma unroll
            for (int db2 = 0; db2 < 4; db2++) {
                uint32_t bH[4], bL[4];
                ldb_v(bH, sb + SM_VH, ks * 16, db2 * 32);
                ldb_v(bL, sb + SM_VL, ks * 16, db2 * 32);
                float* c0 = oacc + db2 * 8;
                mma16816(c0,     aH, bH);     mma16816(c0 + 4, aH, bH + 2);
                mma16816(c0,     aL, bH);     mma16816(c0 + 4, aL, bH + 2);
                mma16816(c0,     aH, bL);     mma16816(c0 + 4, aH, bL + 2);
            }
        }
    }

    // ---- write context ----
    {
        float* crow0 = ctx + ((size_t)b * NN + q0 + wrow0 + gr) * DD + c2;
        float* crow1 = crow0 + 8 * DD;
        #pragma unroll
        for (int db = 0; db < 8; db++) {
            *(float2*)(crow0 + db * 8) = make_float2(oacc[db*4+0], oacc[db*4+1]);
            *(float2*)(crow1 + db * 8) = make_float2(oacc[db*4+2], oacc[db*4+3]);
        }
    }
}

extern "C" void kernel_launch(void* const* d_in, const int* in_sizes, int n_in,
                              void* d_out, int out_size) {
    const float* q  = (const float*)d_in[0];
    const float* k  = (const float*)d_in[1];
    const float* v  = (const float*)d_in[2];
    const float* sc = (const float*)d_in[3];
    float* ctx = (float*)d_out;                          // [16,2048,64]
    float* att = (float*)d_out + (size_t)NB * NN * DD;   // [16,2048,2048]
    cudaFuncSetAttribute(attn_kernel, cudaFuncAttributeMaxDynamicSharedMemorySize, SMEM_TOTAL);
    dim3 grid(NN / BM, NB);
    attn_kernel<<<grid, TB, SMEM_TOTAL>>>(q, k, v, sc, ctx, att);
}

// round 4
// speedup vs baseline: 1.5327x; 1.5327x over previous
#include <cuda_runtime.h>
#include <cuda_bf16.h>
#include <cstdint>

static constexpr int NB = 16, NN = 2048, DD = 64;
static constexpr int BM = 128, BN = 128, NKT = NN / BN, TB = 256;

// Pre-converted bf16 hi/lo panels, SW128-swizzled, tile-blocked:
// g_conv[(t*16 + b)*16 + kt] -> 32KB block {hi 16KB, lo 16KB}, t: 0=Q,1=K,2=V
__device__ __align__(128) uint8_t g_conv[(size_t)3 * 16 * 16 * 32768];

// SMEM layout: Q panels persistent + 2 K/V stages
static constexpr int SM_QH = 0, SM_QL = 16384;
static constexpr int SM_ST = 32768;            // stage s at SM_ST + s*65536
static constexpr int STG = 65536;              // {Kh,Kl,Vh,Vl} 16KB each
static constexpr int SMEM_TOTAL = SM_ST + 2 * STG;   // 163840

__device__ __forceinline__ uint32_t smem_u32(const void* p) {
    uint32_t a;
    asm("{ .reg .u64 t; cvta.to.shared.u64 t, %1; cvt.u32.u64 %0, t; }" : "=r"(a) : "l"(p));
    return a;
}
__device__ __forceinline__ uint32_t sw128(uint32_t bo) { return bo ^ ((bo >> 3) & 0x70); }
__device__ __forceinline__ float ex2f(float x) {
    float y; asm("ex2.approx.f32 %0, %1;" : "=f"(y) : "f"(x)); return y;
}
__device__ __forceinline__ uint32_t bfpack(__nv_bfloat16 a, __nv_bfloat16 b) {
    uint16_t x = *reinterpret_cast<uint16_t*>(&a), y = *reinterpret_cast<uint16_t*>(&b);
    return (uint32_t)x | ((uint32_t)y << 16);
}
__device__ __forceinline__ void split1(float f, __nv_bfloat16& h, __nv_bfloat16& l) {
    h = __float2bfloat16(f);
    l = __float2bfloat16(f - __bfloat162float(h));
}

__device__ __forceinline__ void cpa16(uint32_t s, const void* g) {
    asm volatile("cp.async.cg.shared.global [%0], [%1], 16;" :: "r"(s), "l"(g));
}
#define CP_COMMIT() asm volatile("cp.async.commit_group;" ::: "memory")
#define CP_WAIT0()  asm volatile("cp.async.wait_group 0;" ::: "memory")
#define CP_WAIT1()  asm volatile("cp.async.wait_group 1;" ::: "memory")

__device__ __forceinline__ void stage_copy(uint32_t sdst, const uint8_t* gsrc,
                                           int bytes, int tid) {
    for (int off = tid * 16; off < bytes; off += TB * 16)
        cpa16(sdst + off, gsrc + off);
}

#define LDSM4(r0,r1,r2,r3,ad) \
    asm volatile("ldmatrix.sync.aligned.m8n8.x4.shared.b16 {%0,%1,%2,%3}, [%4];" \
        : "=r"(r0), "=r"(r1), "=r"(r2), "=r"(r3) : "r"(ad))
#define LDSM4T(r0,r1,r2,r3,ad) \
    asm volatile("ldmatrix.sync.aligned.m8n8.x4.trans.shared.b16 {%0,%1,%2,%3}, [%4];" \
        : "=r"(r0), "=r"(r1), "=r"(r2), "=r"(r3) : "r"(ad))

__device__ __forceinline__ void mma16816(float* c, const uint32_t* a, const uint32_t* b) {
    asm volatile("mma.sync.aligned.m16n8k16.row.col.f32.bf16.bf16.f32 "
        "{%0,%1,%2,%3}, {%4,%5,%6,%7}, {%8,%9}, {%0,%1,%2,%3};"
        : "+f"(c[0]), "+f"(c[1]), "+f"(c[2]), "+f"(c[3])
        : "r"(a[0]), "r"(a[1]), "r"(a[2]), "r"(a[3]), "r"(b[0]), "r"(b[1]));
}

__device__ __forceinline__ void lda_frag(uint32_t* fr, uint32_t tile, int row0, int kbyte) {
    int lane = threadIdx.x & 31;
    int r = row0 + (lane & 7) + (lane & 8);
    int cb = kbyte + ((lane & 16) ? 16 : 0);
    LDSM4(fr[0], fr[1], fr[2], fr[3], tile + sw128((uint32_t)(r * 128 + cb)));
}
__device__ __forceinline__ void ldb_k(uint32_t* fr, uint32_t tile, int n0, int kbyte) {
    int lane = threadIdx.x & 31;
    int r = n0 + (lane & 7) + ((lane & 16) ? 8 : 0);
    int cb = kbyte + ((lane & 8) ? 16 : 0);
    LDSM4(fr[0], fr[1], fr[2], fr[3], tile + sw128((uint32_t)(r * 128 + cb)));
}
__device__ __forceinline__ void ldb_v(uint32_t* fr, uint32_t tile, int k0, int dbyte) {
    int lane = threadIdx.x & 31;
    int r = k0 + (lane & 7) + (lane & 8);
    int cb = dbyte + ((lane & 16) ? 16 : 0);
    LDSM4T(fr[0], fr[1], fr[2], fr[3], tile + sw128((uint32_t)(r * 128 + cb)));
}

// S += Q K^T (3-product bf16 split), warp rows [wrow0, wrow0+16)
__device__ __forceinline__ void qk_tile(float* sacc, uint32_t qh, uint32_t ql,
                                        uint32_t kh, uint32_t kl, int wrow0) {
    #pragma unroll
    for (int ks = 0; ks < 4; ks++) {
        uint32_t aH[4], aL[4];
        lda_frag(aH, qh, wrow0, ks * 32);
        lda_frag(aL, ql, wrow0, ks * 32);
        #pragma unroll
        for (int nb2 = 0; nb2 < 8; nb2++) {
            uint32_t bH[4], bL[4];
            ldb_k(bH, kh, nb2 * 16, ks * 32);
            ldb_k(bL, kl, nb2 * 16, ks * 32);
            float* c0 = sacc + nb2 * 8;
            mma16816(c0,     aH, bH);     mma16816(c0 + 4, aH, bH + 2);
            mma16816(c0,     aL, bH);     mma16816(c0 + 4, aL, bH + 2);
            mma16816(c0,     aH, bL);     mma16816(c0 + 4, aH, bL + 2);
        }
    }
}

// -------------------------------------------------- pre-convert fp32 -> bf16 hi/lo
__global__ void __launch_bounds__(TB)
conv_kernel(const float* __restrict__ q, const float* __restrict__ k,
            const float* __restrict__ v)
{
    const int kt = blockIdx.x, b = blockIdx.y, t = blockIdx.z;
    const float* src = (t == 0 ? q : (t == 1 ? k : v)) + ((size_t)b * NN + kt * BM) * DD;
    uint8_t* dH = g_conv + (((size_t)t * 16 + b) * 16 + kt) * 32768;
    uint8_t* dL = dH + 16384;
    for (int e = threadIdx.x; e < BM * 16; e += TB) {
        int row = e >> 4, c4 = (e & 15) << 2;
        float4 f = *(const float4*)(src + row * DD + c4);
        __nv_bfloat16 h0,h1,h2,h3,l0,l1,l2,l3;
        split1(f.x,h0,l0); split1(f.y,h1,l1); split1(f.z,h2,l2); split1(f.w,h3,l3);
        uint32_t bo = (uint32_t)(row * 128 + c4 * 2);
        uint32_t s0 = sw128(bo), s1 = sw128(bo + 4);
        *(uint32_t*)(dH + s0) = bfpack(h0, h1);
        *(uint32_t*)(dH + s1) = bfpack(h2, h3);
        *(uint32_t*)(dL + s0) = bfpack(l0, l1);
        *(uint32_t*)(dL + s1) = bfpack(l2, l3);
    }
}

// -------------------------------------------------- main attention kernel
__global__ void __launch_bounds__(TB, 1)
attn_kernel(const float* __restrict__ scp, float* __restrict__ ctx,
            float* __restrict__ att)
{
    extern __shared__ char smem[];
    const uint32_t sb = smem_u32(smem);
    const int tid = threadIdx.x, lane = tid & 31, wid = tid >> 5;
    const int wrow0 = wid * 16;
    const int gr = lane >> 2, c2 = (lane & 3) * 2;
    const int b = blockIdx.y, q0 = blockIdx.x * BM;
    const float cexp = scp[0] * 1.4426950408889634f;

    const uint8_t* qblk = g_conv + (((size_t)0 * 16 + b) * 16 + blockIdx.x) * 32768;
    const uint8_t* kbase = g_conv + (((size_t)1 * 16 + b) * 16) * 32768;
    const uint8_t* vbase = g_conv + (((size_t)2 * 16 + b) * 16) * 32768;

    // group 0: Q panels (32KB) + K tile 0 (32KB)
    stage_copy(sb + SM_QH, qblk, 32768, tid);
    stage_copy(sb + SM_ST, kbase, 32768, tid);
    CP_COMMIT();

    float rs0 = 0.f, rs1 = 0.f;

    // ================= pass 1: row sums (K only) =================
    for (int kt = 0; kt < NKT; kt++) {
        const uint32_t stg = sb + SM_ST + (uint32_t)(kt & 1) * STG;
        if (kt + 1 < NKT) {
            stage_copy(sb + SM_ST + (uint32_t)((kt + 1) & 1) * STG,
                       kbase + (size_t)(kt + 1) * 32768, 32768, tid);
            CP_COMMIT();
            CP_WAIT1();
        } else {
            CP_WAIT0();
        }
        __syncthreads();

        float sacc[64];
        #pragma unroll
        for (int i = 0; i < 64; i++) sacc[i] = 0.f;
        qk_tile(sacc, sb + SM_QH, sb + SM_QL, stg, stg + 16384, wrow0);
        #pragma unroll
        for (int nb = 0; nb < 16; nb++) {
            rs0 += ex2f(sacc[nb*4+0] * cexp) + ex2f(sacc[nb*4+1] * cexp);
            rs1 += ex2f(sacc[nb*4+2] * cexp) + ex2f(sacc[nb*4+3] * cexp);
        }
        __syncthreads();
    }

    // prefetch pass-2 tile 0 (K+V, 64KB) into stage 0, then reduce row sums
    stage_copy(sb + SM_ST,         kbase, 32768, tid);
    stage_copy(sb + SM_ST + 32768, vbase, 32768, tid);
    CP_COMMIT();

    rs0 += __shfl_xor_sync(0xffffffff, rs0, 1);
    rs0 += __shfl_xor_sync(0xffffffff, rs0, 2);
    rs1 += __shfl_xor_sync(0xffffffff, rs1, 1);
    rs1 += __shfl_xor_sync(0xffffffff, rs1, 2);
    const float li0 = 1.0f / rs0, li1 = 1.0f / rs1;

    float oacc[32];
    #pragma unroll
    for (int i = 0; i < 32; i++) oacc[i] = 0.f;

    // ================= pass 2: attention + O =================
    for (int kt = 0; kt < NKT; kt++) {
        const uint32_t stg = sb + SM_ST + (uint32_t)(kt & 1) * STG;
        if (kt + 1 < NKT) {
            const uint32_t nstg = sb + SM_ST + (uint32_t)((kt + 1) & 1) * STG;
            stage_copy(nstg,         kbase + (size_t)(kt + 1) * 32768, 32768, tid);
            stage_copy(nstg + 32768, vbase + (size_t)(kt + 1) * 32768, 32768, tid);
            CP_COMMIT();
            CP_WAIT1();
        } else {
            CP_WAIT0();
        }
        __syncthreads();

        float sacc[64];
        #pragma unroll
        for (int i = 0; i < 64; i++) sacc[i] = 0.f;
        qk_tile(sacc, sb + SM_QH, sb + SM_QL, stg, stg + 16384, wrow0);

        // exp, normalize, write attention, pack P into a-frags (hi/lo)
        uint32_t ph[32], pl[32];
        {
            float* arow0 = att + ((size_t)b * NN + q0 + wrow0 + gr) * NN + kt * BN + c2;
            float* arow1 = arow0 + (size_t)8 * NN;
            #pragma unroll
            for (int nb = 0; nb < 16; nb++) {
                float p0 = ex2f(sacc[nb*4+0] * cexp) * li0;
                float p1 = ex2f(sacc[nb*4+1] * cexp) * li0;
                float p2 = ex2f(sacc[nb*4+2] * cexp) * li1;
                float p3 = ex2f(sacc[nb*4+3] * cexp) * li1;
                *(float2*)(arow0 + nb * 8) = make_float2(p0, p1);
                *(float2*)(arow1 + nb * 8) = make_float2(p2, p3);
                __nv_bfloat16 h0,h1,h2,h3,l0,l1,l2,l3;
                split1(p0,h0,l0); split1(p1,h1,l1); split1(p2,h2,l2); split1(p3,h3,l3);
                int ks = nb >> 1, hf2 = (nb & 1) * 2;
                ph[ks*4 + hf2 + 0] = bfpack(h0, h1);
                ph[ks*4 + hf2 + 1] = bfpack(h2, h3);
                pl[ks*4 + hf2 + 0] = bfpack(l0, l1);
                pl[ks*4 + hf2 + 1] = bfpack(l2, l3);
            }
        }

        // O += P V  (3-product split)
        const uint32_t vh = stg + 32768, vl = stg + 49152;
        #pragma unroll
        for (int ks = 0; ks < 8; ks++) {
            const uint32_t* aH = ph + ks * 4;
            const uint32_t* aL = pl + ks * 4;
            #pragma unroll
            for (int db2 = 0; db2 < 4; db2++) {
                uint32_t bH[4], bL[4];
                ldb_v(bH, vh, ks * 16, db2 * 32);
                ldb_v(bL, vl, ks * 16, db2 * 32);
                float* c0 = oacc + db2 * 8;
                mma16816(c0,     aH, bH);     mma16816(c0 + 4, aH, bH + 2);
                mma16816(c0,     aL, bH);     mma16816(c0 + 4, aL, bH + 2);
                mma16816(c0,     aH, bL);     mma16816(c0 + 4, aH, bL + 2);
            }
        }
        __syncthreads();
    }

    // ---- write context ----
    {
        float* crow0 = ctx + ((size_t)b * NN + q0 + wrow0 + gr) * DD + c2;
        float* crow1 = crow0 + 8 * DD;
        #pragma unroll
        for (int db = 0; db < 8; db++) {
            *(float2*)(crow0 + db * 8) = make_float2(oacc[db*4+0], oacc[db*4+1]);
            *(float2*)(crow1 + db * 8) = make_float2(oacc[db*4+2], oacc[db*4+3]);
        }
    }
}

extern "C" void kernel_launch(void* const* d_in, const int* in_sizes, int n_in,
                              void* d_out, int out_size) {
    const float* q  = (const float*)d_in[0];
    const float* k  = (const float*)d_in[1];
    const float* v  = (const float*)d_in[2];
    const float* sc = (const float*)d_in[3];
    float* ctx = (float*)d_out;                          // [16,2048,64]
    float* att = (float*)d_out + (size_t)NB * NN * DD;   // [16,2048,2048]

    conv_kernel<<<dim3(NKT, NB, 3), TB>>>(q, k, v);

    cudaFuncSetAttribute(attn_kernel, cudaFuncAttributeMaxDynamicSharedMemorySize, SMEM_TOTAL);
    dim3 grid(NN / BM, NB);
    attn_kernel<<<grid, TB, SMEM_TOTAL>>>(sc, ctx, att);
}

// round 6
// speedup vs baseline: 1.5468x; 1.0092x over previous
#include <cuda_runtime.h>
#include <cuda_bf16.h>
#include <cstdint>

static constexpr int NB = 16, NN = 2048, DD = 64;
static constexpr int BM = 128, BN = 128, NKT = NN / BN, TB = 512;

// Pre-converted bf16 hi/lo panels, SW128-swizzled, tile-blocked:
// g_conv[(t*16 + b)*16 + kt] -> 32KB block {hi 16KB, lo 16KB}, t: 0=Q,1=K,2=V
__device__ __align__(128) uint8_t g_conv[(size_t)3 * 16 * 16 * 32768];

// SMEM layout: Q panels persistent + 2 K/V stages + reduce scratch
static constexpr int SM_QH = 0, SM_QL = 16384;
static constexpr int SM_ST = 32768;            // stage s at SM_ST + s*65536
static constexpr int STG = 65536;              // {Kh,Kl,Vh,Vl} 16KB each
static constexpr int SM_L = SM_ST + 2 * STG;   // 2*128 floats row-sum partials
static constexpr int SMEM_TOTAL = SM_L + 1024; // 164864

__device__ __forceinline__ uint32_t smem_u32(const void* p) {
    uint32_t a;
    asm("{ .reg .u64 t; cvta.to.shared.u64 t, %1; cvt.u32.u64 %0, t; }" : "=r"(a) : "l"(p));
    return a;
}
__device__ __forceinline__ uint32_t sw128(uint32_t bo) { return bo ^ ((bo >> 3) & 0x70); }
__device__ __forceinline__ float ex2f(float x) {
    float y; asm("ex2.approx.f32 %0, %1;" : "=f"(y) : "f"(x)); return y;
}
__device__ __forceinline__ uint32_t bfpack(__nv_bfloat16 a, __nv_bfloat16 b) {
    uint16_t x = *reinterpret_cast<uint16_t*>(&a), y = *reinterpret_cast<uint16_t*>(&b);
    return (uint32_t)x | ((uint32_t)y << 16);
}
__device__ __forceinline__ void split1(float f, __nv_bfloat16& h, __nv_bfloat16& l) {
    h = __float2bfloat16(f);
    l = __float2bfloat16(f - __bfloat162float(h));
}

__device__ __forceinline__ void cpa16(uint32_t s, const void* g) {
    asm volatile("cp.async.cg.shared.global [%0], [%1], 16;" :: "r"(s), "l"(g));
}
#define CP_COMMIT() asm volatile("cp.async.commit_group;" ::: "memory")
#define CP_WAIT0()  asm volatile("cp.async.wait_group 0;" ::: "memory")
#define CP_WAIT1()  asm volatile("cp.async.wait_group 1;" ::: "memory")

__device__ __forceinline__ void stage_copy(uint32_t sdst, const uint8_t* gsrc,
                                           int bytes, int tid) {
    for (int off = tid * 16; off < bytes; off += TB * 16)
        cpa16(sdst + off, gsrc + off);
}

#define LDSM4(r0,r1,r2,r3,ad) \
    asm volatile("ldmatrix.sync.aligned.m8n8.x4.shared.b16 {%0,%1,%2,%3}, [%4];" \
        : "=r"(r0), "=r"(r1), "=r"(r2), "=r"(r3) : "r"(ad))
#define LDSM4T(r0,r1,r2,r3,ad) \
    asm volatile("ldmatrix.sync.aligned.m8n8.x4.trans.shared.b16 {%0,%1,%2,%3}, [%4];" \
        : "=r"(r0), "=r"(r1), "=r"(r2), "=r"(r3) : "r"(ad))

__device__ __forceinline__ void mma16816(float* c, const uint32_t* a, const uint32_t* b) {
    asm volatile("mma.sync.aligned.m16n8k16.row.col.f32.bf16.bf16.f32 "
        "{%0,%1,%2,%3}, {%4,%5,%6,%7}, {%8,%9}, {%0,%1,%2,%3};"
        : "+f"(c[0]), "+f"(c[1]), "+f"(c[2]), "+f"(c[3])
        : "r"(a[0]), "r"(a[1]), "r"(a[2]), "r"(a[3]), "r"(b[0]), "r"(b[1]));
}

__device__ __forceinline__ void lda_frag(uint32_t* fr, uint32_t tile, int row0, int kbyte) {
    int lane = threadIdx.x & 31;
    int r = row0 + (lane & 7) + (lane & 8);
    int cb = kbyte + ((lane & 16) ? 16 : 0);
    LDSM4(fr[0], fr[1], fr[2], fr[3], tile + sw128((uint32_t)(r * 128 + cb)));
}
__device__ __forceinline__ void ldb_k(uint32_t* fr, uint32_t tile, int n0, int kbyte) {
    int lane = threadIdx.x & 31;
    int r = n0 + (lane & 7) + ((lane & 16) ? 8 : 0);
    int cb = kbyte + ((lane & 8) ? 16 : 0);
    LDSM4(fr[0], fr[1], fr[2], fr[3], tile + sw128((uint32_t)(r * 128 + cb)));
}
__device__ __forceinline__ void ldb_v(uint32_t* fr, uint32_t tile, int k0, int dbyte) {
    int lane = threadIdx.x & 31;
    int r = k0 + (lane & 7) + (lane & 8);
    int cb = dbyte + ((lane & 16) ? 16 : 0);
    LDSM4T(fr[0], fr[1], fr[2], fr[3], tile + sw128((uint32_t)(r * 128 + cb)));
}

// S += Q K^T over this warp's 16 rows x 64-col n-half (3-product bf16 split)
__device__ __forceinline__ void qk_half(float* sacc, uint32_t qh, uint32_t ql,
                                        uint32_t kh, uint32_t kl, int wr0, int n0) {
    #pragma unroll
    for (int ks = 0; ks < 4; ks++) {
        uint32_t aH[4], aL[4];
        lda_frag(aH, qh, wr0, ks * 32);
        lda_frag(aL, ql, wr0, ks * 32);
        #pragma unroll
        for (int nb2 = 0; nb2 < 4; nb2++) {
            uint32_t bH[4], bL[4];
            ldb_k(bH, kh, n0 + nb2 * 16, ks * 32);
            ldb_k(bL, kl, n0 + nb2 * 16, ks * 32);
            float* c0 = sacc + nb2 * 8;
            mma16816(c0,     aH, bH);     mma16816(c0 + 4, aH, bH + 2);
            mma16816(c0,     aL, bH);     mma16816(c0 + 4, aL, bH + 2);
            mma16816(c0,     aH, bL);     mma16816(c0 + 4, aH, bL + 2);
        }
    }
}

// -------------------------------------------------- pre-convert fp32 -> bf16 hi/lo
__global__ void __launch_bounds__(256)
conv_kernel(const float* __restrict__ q, const float* __restrict__ k,
            const float* __restrict__ v)
{
    const int kt = blockIdx.x, b = blockIdx.y, t = blockIdx.z;
    const float* src = (t == 0 ? q : (t == 1 ? k : v)) + ((size_t)b * NN + kt * BM) * DD;
    uint8_t* dH = g_conv + (((size_t)t * 16 + b) * 16 + kt) * 32768;
    uint8_t* dL = dH + 16384;
    for (int e = threadIdx.x; e < BM * 16; e += 256) {
        int row = e >> 4, c4 = (e & 15) << 2;
        float4 f = *(const float4*)(src + row * DD + c4);
        __nv_bfloat16 h0,h1,h2,h3,l0,l1,l2,l3;
        split1(f.x,h0,l0); split1(f.y,h1,l1); split1(f.z,h2,l2); split1(f.w,h3,l3);
        uint32_t bo = (uint32_t)(row * 128 + c4 * 2);
        uint32_t s0 = sw128(bo), s1 = sw128(bo + 4);
        *(uint32_t*)(dH + s0) = bfpack(h0, h1);
        *(uint32_t*)(dH + s1) = bfpack(h2, h3);
        *(uint32_t*)(dL + s0) = bfpack(l0, l1);
        *(uint32_t*)(dL + s1) = bfpack(l2, l3);
    }
}

// -------------------------------------------------- main attention kernel
__global__ void __launch_bounds__(TB, 1)
attn_kernel(const float* __restrict__ scp, float* __restrict__ ctx,
            float* __restrict__ att)
{
    extern __shared__ char smem[];
    const uint32_t sb = smem_u32(smem);
    const int tid = threadIdx.x, lane = tid & 31, wid = tid >> 5;
    const int wr0 = (wid >> 1) * 16;       // warp's first q-row in tile
    const int nh = wid & 1;                // n-half (== k-half for PV)
    const int n0 = nh * 64;
    const int gr = lane >> 2, c2 = (lane & 3) * 2;
    const int b = blockIdx.y, q0 = blockIdx.x * BM;
    const float cexp = scp[0] * 1.4426950408889634f;

    const uint8_t* qblk = g_conv + (((size_t)0 * 16 + b) * 16 + blockIdx.x) * 32768;
    const uint8_t* kbase = g_conv + (((size_t)1 * 16 + b) * 16) * 32768;
    const uint8_t* vbase = g_conv + (((size_t)2 * 16 + b) * 16) * 32768;

    // group 0: Q panels (32KB) + K tile 0 (32KB)
    stage_copy(sb + SM_QH, qblk, 32768, tid);
    stage_copy(sb + SM_ST, kbase, 32768, tid);
    CP_COMMIT();

    float rs0 = 0.f, rs1 = 0.f;

    // ================= pass 1: row sums (K only) =================
    for (int kt = 0; kt < NKT; kt++) {
        const uint32_t stg = sb + SM_ST + (uint32_t)(kt & 1) * STG;
        if (kt + 1 < NKT) {
            stage_copy(sb + SM_ST + (uint32_t)((kt + 1) & 1) * STG,
                       kbase + (size_t)(kt + 1) * 32768, 32768, tid);
            CP_COMMIT();
            CP_WAIT1();
        } else {
            CP_WAIT0();
        }
        __syncthreads();

        float sacc[32];
        #pragma unroll
        for (int i = 0; i < 32; i++) sacc[i] = 0.f;
        qk_half(sacc, sb + SM_QH, sb + SM_QL, stg, stg + 16384, wr0, n0);
        #pragma unroll
        for (int nb = 0; nb < 8; nb++) {
            rs0 += ex2f(sacc[nb*4+0] * cexp) + ex2f(sacc[nb*4+1] * cexp);
            rs1 += ex2f(sacc[nb*4+2] * cexp) + ex2f(sacc[nb*4+3] * cexp);
        }
        __syncthreads();
    }

    // prefetch pass-2 tile 0 (K+V) while reducing row sums
    stage_copy(sb + SM_ST,         kbase, 32768, tid);
    stage_copy(sb + SM_ST + 32768, vbase, 32768, tid);
    CP_COMMIT();

    rs0 += __shfl_xor_sync(0xffffffff, rs0, 1);
    rs0 += __shfl_xor_sync(0xffffffff, rs0, 2);
    rs1 += __shfl_xor_sync(0xffffffff, rs1, 1);
    rs1 += __shfl_xor_sync(0xffffffff, rs1, 2);
    // combine the two n-half partials via SMEM
    if ((lane & 3) == 0) {
        *(float*)(smem + SM_L + (nh * 128 + wr0 + gr)     * 4) = rs0;
        *(float*)(smem + SM_L + (nh * 128 + wr0 + 8 + gr) * 4) = rs1;
    }
    __syncthreads();
    const float li0 = 1.0f / (*(float*)(smem + SM_L + (wr0 + gr) * 4) +
                              *(float*)(smem + SM_L + (128 + wr0 + gr) * 4));
    const float li1 = 1.0f / (*(float*)(smem + SM_L + (wr0 + 8 + gr) * 4) +
                              *(float*)(smem + SM_L + (128 + wr0 + 8 + gr) * 4));

    float oacc[32];
    #pragma unroll
    for (int i = 0; i < 32; i++) oacc[i] = 0.f;

    // ================= pass 2: attention + O =================
    for (int kt = 0; kt < NKT; kt++) {
        const uint32_t stg = sb + SM_ST + (uint32_t)(kt & 1) * STG;
        if (kt + 1 < NKT) {
            const uint32_t nstg = sb + SM_ST + (uint32_t)((kt + 1) & 1) * STG;
            stage_copy(nstg,         kbase + (size_t)(kt + 1) * 32768, 32768, tid);
            stage_copy(nstg + 32768, vbase + (size_t)(kt + 1) * 32768, 32768, tid);
            CP_COMMIT();
            CP_WAIT1();
        } else {
            CP_WAIT0();
        }
        __syncthreads();

        float sacc[32];
        #pragma unroll
        for (int i = 0; i < 32; i++) sacc[i] = 0.f;
        qk_half(sacc, sb + SM_QH, sb + SM_QL, stg, stg + 16384, wr0, n0);

        // exp, normalize, write attention, pack P into a-frags (hi/lo)
        uint32_t ph[16], pl[16];
        {
            float* arow0 = att + ((size_t)b * NN + q0 + wr0 + gr) * NN + kt * BN + n0 + c2;
            float* arow1 = arow0 + (size_t)8 * NN;
            #pragma unroll
            for (int nb = 0; nb < 8; nb++) {
                float p0 = ex2f(sacc[nb*4+0] * cexp) * li0;
                float p1 = ex2f(sacc[nb*4+1] * cexp) * li0;
                float p2 = ex2f(sacc[nb*4+2] * cexp) * li1;
                float p3 = ex2f(sacc[nb*4+3] * cexp) * li1;
                *(float2*)(arow0 + nb * 8) = make_float2(p0, p1);
                *(float2*)(arow1 + nb * 8) = make_float2(p2, p3);
                __nv_bfloat16 h0,h1,h2,h3,l0,l1,l2,l3;
                split1(p0,h0,l0); split1(p1,h1,l1); split1(p2,h2,l2); split1(p3,h3,l3);
                int ks = nb >> 1, hf2 = (nb & 1) * 2;
                ph[ks*4 + hf2 + 0] = bfpack(h0, h1);
                ph[ks*4 + hf2 + 1] = bfpack(h2, h3);
                pl[ks*4 + hf2 + 0] = bfpack(l0, l1);
                pl[ks*4 + hf2 + 1] = bfpack(l2, l3);
            }
        }

        // O += P V over this warp's k-half (3-product split)
        const uint32_t vh = stg + 32768, vl = stg + 49152;
        #pragma unroll
        for (int ks = 0; ks < 4; ks++) {
            const uint32_t* aH = ph + ks * 4;
            const uint32_t* aL = pl + ks * 4;
            const int k0 = n0 + ks * 16;
            #pragma unroll
            for (int db2 = 0; db2 < 4; db2++) {
                uint32_t bH[4], bL[4];
                ldb_v(bH, vh, k0, db2 * 32);
                ldb_v(bL, vl, k0, db2 * 32);
                float* c0 = oacc + db2 * 8;
                mma16816(c0,     aH, bH);     mma16816(c0 + 4, aH, bH + 2);
                mma16816(c0,     aL, bH);     mma16816(c0 + 4, aL, bH + 2);
                mma16816(c0,     aH, bL);     mma16816(c0 + 4, aH, bL + 2);
            }
        }
        __syncthreads();
    }

    // ---- reduce O across the k-half warp pairs, write context ----
    {
        char* red = smem + SM_ST + (size_t)(wid >> 1) * 8192;   // generic pointer!
        if (nh == 1) {
            #pragma unroll
            for (int db = 0; db < 8; db++) {
                *(float2*)(red + ((uint32_t)(gr)     * 64 + db * 8 + c2) * 4) =
                    make_float2(oacc[db*4+0], oacc[db*4+1]);
                *(float2*)(red + ((uint32_t)(gr + 8) * 64 + db * 8 + c2) * 4) =
                    make_float2(oacc[db*4+2], oacc[db*4+3]);
            }
        }
        __syncthreads();
        if (nh == 0) {
            float* crow0 = ctx + ((size_t)b * NN + q0 + wr0 + gr) * DD + c2;
            float* crow1 = crow0 + 8 * DD;
            #pragma unroll
            for (int db = 0; db < 8; db++) {
                float2 a0 = *(float2*)(red + ((uint32_t)(gr)     * 64 + db * 8 + c2) * 4);
                float2 a1 = *(float2*)(red + ((uint32_t)(gr + 8) * 64 + db * 8 + c2) * 4);
                *(float2*)(crow0 + db * 8) = make_float2(oacc[db*4+0] + a0.x, oacc[db*4+1] + a0.y);
                *(float2*)(crow1 + db * 8) = make_float2(oacc[db*4+2] + a1.x, oacc[db*4+3] + a1.y);
            }
        }
    }
}

extern "C" void kernel_launch(void* const* d_in, const int* in_sizes, int n_in,
                              void* d_out, int out_size) {
    const float* q  = (const float*)d_in[0];
    const float* k  = (const float*)d_in[1];
    const float* v  = (const float*)d_in[2];
    const float* sc = (const float*)d_in[3];
    float* ctx = (float*)d_out;                          // [16,2048,64]
    float* att = (float*)d_out + (size_t)NB * NN * DD;   // [16,2048,2048]

    conv_kernel<<<dim3(NKT, NB, 3), 256>>>(q, k, v);

    cudaFuncSetAttribute(attn_kernel, cudaFuncAttributeMaxDynamicSharedMemorySize, SMEM_TOTAL);
    dim3 grid(NN / BM, NB);
    attn_kernel<<<grid, TB, SMEM_TOTAL>>>(sc, ctx, att);
}

// round 7
// speedup vs baseline: 1.7150x; 1.1087x over previous
#include <cuda_runtime.h>
#include <cuda_bf16.h>
#include <cstdint>

static constexpr int NB = 16, NN = 2048, DD = 64;
static constexpr int BM = 128, BN = 128, NKT = NN / BN, TB = 512;

// Pre-converted bf16 hi/lo panels, SW128-swizzled, tile-blocked:
// g_conv[(t*16 + b)*16 + kt] -> 32KB block {hi 16KB, lo 16KB}, t: 0=Q,1=K,2=V
__device__ __align__(128) uint8_t g_conv[(size_t)3 * 16 * 16 * 32768];

// SMEM layout:
//   [0, 32K)              : QH 16K, QL 16K (shared, read-only after init)
//   GB(g) = 32768 + g*98304, 96KB per group:
//     pass1: Kh stage s @ GB + s*16384          (s = 0,1)
//     pass2: Kh @ GB, Kl @ GB+16384 (single K stage)
//            V stage s @ GB+32768+s*32768: {Vh, Vl}  (s = 0,1)
//   SM_L = 229376 : per-group row-sum partials (g*512 + (nh*64+lrow)*4)
static constexpr int SM_QH = 0, SM_QL = 16384;
static constexpr int GB0 = 32768, GSZ = 98304;
static constexpr int SM_L = GB0 + 2 * GSZ;          // 229376
static constexpr int SMEM_TOTAL = SM_L + 1024;      // 230400 (< 227KB cap)

__device__ __forceinline__ uint32_t smem_u32(const void* p) {
    uint32_t a;
    asm("{ .reg .u64 t; cvta.to.shared.u64 t, %1; cvt.u32.u64 %0, t; }" : "=r"(a) : "l"(p));
    return a;
}
__device__ __forceinline__ uint32_t sw128(uint32_t bo) { return bo ^ ((bo >> 3) & 0x70); }
__device__ __forceinline__ float ex2f(float x) {
    float y; asm("ex2.approx.f32 %0, %1;" : "=f"(y) : "f"(x)); return y;
}
__device__ __forceinline__ uint32_t bfpack(__nv_bfloat16 a, __nv_bfloat16 b) {
    uint16_t x = *reinterpret_cast<uint16_t*>(&a), y = *reinterpret_cast<uint16_t*>(&b);
    return (uint32_t)x | ((uint32_t)y << 16);
}
__device__ __forceinline__ void split1(float f, __nv_bfloat16& h, __nv_bfloat16& l) {
    h = __float2bfloat16(f);
    l = __float2bfloat16(f - __bfloat162float(h));
}

__device__ __forceinline__ void cpa16(uint32_t s, const void* g) {
    asm volatile("cp.async.cg.shared.global [%0], [%1], 16;" :: "r"(s), "l"(g));
}
#define CP_COMMIT() asm volatile("cp.async.commit_group;" ::: "memory")
#define CP_WAIT0()  asm volatile("cp.async.wait_group 0;" ::: "memory")
#define CP_WAIT1()  asm volatile("cp.async.wait_group 1;" ::: "memory")
#define BARG(g) asm volatile("bar.sync %0, %1;" :: "r"((g) + 1), "r"(256) : "memory")

// copy using only this group's 256 threads
__device__ __forceinline__ void gcopy(uint32_t sdst, const uint8_t* gsrc,
                                      int bytes, int gtid) {
    for (int off = gtid * 16; off < bytes; off += 256 * 16)
        cpa16(sdst + off, gsrc + off);
}

#define LDSM4(r0,r1,r2,r3,ad) \
    asm volatile("ldmatrix.sync.aligned.m8n8.x4.shared.b16 {%0,%1,%2,%3}, [%4];" \
        : "=r"(r0), "=r"(r1), "=r"(r2), "=r"(r3) : "r"(ad))
#define LDSM4T(r0,r1,r2,r3,ad) \
    asm volatile("ldmatrix.sync.aligned.m8n8.x4.trans.shared.b16 {%0,%1,%2,%3}, [%4];" \
        : "=r"(r0), "=r"(r1), "=r"(r2), "=r"(r3) : "r"(ad))

__device__ __forceinline__ void mma16816(float* c, const uint32_t* a, const uint32_t* b) {
    asm volatile("mma.sync.aligned.m16n8k16.row.col.f32.bf16.bf16.f32 "
        "{%0,%1,%2,%3}, {%4,%5,%6,%7}, {%8,%9}, {%0,%1,%2,%3};"
        : "+f"(c[0]), "+f"(c[1]), "+f"(c[2]), "+f"(c[3])
        : "r"(a[0]), "r"(a[1]), "r"(a[2]), "r"(a[3]), "r"(b[0]), "r"(b[1]));
}

__device__ __forceinline__ void lda_frag(uint32_t* fr, uint32_t tile, int row0, int kbyte) {
    int lane = threadIdx.x & 31;
    int r = row0 + (lane & 7) + (lane & 8);
    int cb = kbyte + ((lane & 16) ? 16 : 0);
    LDSM4(fr[0], fr[1], fr[2], fr[3], tile + sw128((uint32_t)(r * 128 + cb)));
}
__device__ __forceinline__ void ldb_k(uint32_t* fr, uint32_t tile, int n0, int kbyte) {
    int lane = threadIdx.x & 31;
    int r = n0 + (lane & 7) + ((lane & 16) ? 8 : 0);
    int cb = kbyte + ((lane & 8) ? 16 : 0);
    LDSM4(fr[0], fr[1], fr[2], fr[3], tile + sw128((uint32_t)(r * 128 + cb)));
}
__device__ __forceinline__ void ldb_v(uint32_t* fr, uint32_t tile, int k0, int dbyte) {
    int lane = threadIdx.x & 31;
    int r = k0 + (lane & 7) + (lane & 8);
    int cb = dbyte + ((lane & 16) ? 16 : 0);
    LDSM4T(fr[0], fr[1], fr[2], fr[3], tile + sw128((uint32_t)(r * 128 + cb)));
}

// pass-1: single-product QK (Qh*Kh) over 16 rows x 64-col n-half
__device__ __forceinline__ void qk_one(float* sacc, uint32_t qh, uint32_t kh,
                                       int wr0, int n0) {
    #pragma unroll
    for (int ks = 0; ks < 4; ks++) {
        uint32_t aH[4];
        lda_frag(aH, qh, wr0, ks * 32);
        #pragma unroll
        for (int nb2 = 0; nb2 < 4; nb2++) {
            uint32_t bH[4];
            ldb_k(bH, kh, n0 + nb2 * 16, ks * 32);
            float* c0 = sacc + nb2 * 8;
            mma16816(c0, aH, bH);     mma16816(c0 + 4, aH, bH + 2);
        }
    }
}
// pass-2: 3-product QK
__device__ __forceinline__ void qk_three(float* sacc, uint32_t qh, uint32_t ql,
                                         uint32_t kh, uint32_t kl, int wr0, int n0) {
    #pragma unroll
    for (int ks = 0; ks < 4; ks++) {
        uint32_t aH[4], aL[4];
        lda_frag(aH, qh, wr0, ks * 32);
        lda_frag(aL, ql, wr0, ks * 32);
        #pragma unroll
        for (int nb2 = 0; nb2 < 4; nb2++) {
            uint32_t bH[4], bL[4];
            ldb_k(bH, kh, n0 + nb2 * 16, ks * 32);
            ldb_k(bL, kl, n0 + nb2 * 16, ks * 32);
            float* c0 = sacc + nb2 * 8;
            mma16816(c0,     aH, bH);     mma16816(c0 + 4, aH, bH + 2);
            mma16816(c0,     aL, bH);     mma16816(c0 + 4, aL, bH + 2);
            mma16816(c0,     aH, bL);     mma16816(c0 + 4, aH, bL + 2);
        }
    }
}

// -------------------------------------------------- pre-convert fp32 -> bf16 hi/lo
__global__ void __launch_bounds__(256)
conv_kernel(const float* __restrict__ q, const float* __restrict__ k,
            const float* __restrict__ v)
{
    const int kt = blockIdx.x, b = blockIdx.y, t = blockIdx.z;
    const float* src = (t == 0 ? q : (t == 1 ? k : v)) + ((size_t)b * NN + kt * BM) * DD;
    uint8_t* dH = g_conv + (((size_t)t * 16 + b) * 16 + kt) * 32768;
    uint8_t* dL = dH + 16384;
    for (int e = threadIdx.x; e < BM * 16; e += 256) {
        int row = e >> 4, c4 = (e & 15) << 2;
        float4 f = *(const float4*)(src + row * DD + c4);
        __nv_bfloat16 h0,h1,h2,h3,l0,l1,l2,l3;
        split1(f.x,h0,l0); split1(f.y,h1,l1); split1(f.z,h2,l2); split1(f.w,h3,l3);
        uint32_t bo = (uint32_t)(row * 128 + c4 * 2);
        uint32_t s0 = sw128(bo), s1 = sw128(bo + 4);
        *(uint32_t*)(dH + s0) = bfpack(h0, h1);
        *(uint32_t*)(dH + s1) = bfpack(h2, h3);
        *(uint32_t*)(dL + s0) = bfpack(l0, l1);
        *(uint32_t*)(dL + s1) = bfpack(l2, l3);
    }
}

// -------------------------------------------------- main attention kernel
__global__ void __launch_bounds__(TB, 1)
attn_kernel(const float* __restrict__ scp, float* __restrict__ ctx,
            float* __restrict__ att)
{
    extern __shared__ char smem[];
    const uint32_t sb = smem_u32(smem);
    const int tid = threadIdx.x, lane = tid & 31, wid = tid >> 5;
    const int g = wid >> 3;                    // group 0/1
    const int gtid = tid & 255;
    const int lwr0 = ((wid >> 1) & 3) * 16;    // row-block within group
    const int wr0 = g * 64 + lwr0;             // warp's first q-row in tile
    const int nh = wid & 1;                    // n-half (== k-half for PV)
    const int n0 = nh * 64;
    const int gr = lane >> 2, c2 = (lane & 3) * 2;
    const int b = blockIdx.y, q0 = blockIdx.x * BM;
    const float cexp = scp[0] * 1.4426950408889634f;

    const uint32_t GB = sb + GB0 + (uint32_t)g * GSZ;
    const uint8_t* qblk = g_conv + (((size_t)0 * 16 + b) * 16 + blockIdx.x) * 32768;
    const uint8_t* kbase = g_conv + (((size_t)1 * 16 + b) * 16) * 32768;
    const uint8_t* vbase = g_conv + (((size_t)2 * 16 + b) * 16) * 32768;

    // ---- shared Q load, then groups decouple completely ----
    {
        for (int off = tid * 16; off < 32768; off += TB * 16)
            cpa16(sb + SM_QH + off, qblk + off);
        CP_COMMIT();
        CP_WAIT0();
        __syncthreads();
    }

    float rs0 = 0.f, rs1 = 0.f;

    // ================= pass 1: row sums (Kh only, 1-product) =================
    gcopy(GB, kbase, 16384, gtid);      // Kh tile 0 -> stage 0
    CP_COMMIT();
    for (int kt = 0; kt < NKT; kt++) {
        const uint32_t kst = GB + (uint32_t)(kt & 1) * 16384;
        if (kt + 1 < NKT) {
            gcopy(GB + (uint32_t)((kt + 1) & 1) * 16384,
                  kbase + (size_t)(kt + 1) * 32768, 16384, gtid);
            CP_COMMIT();
            CP_WAIT1();
        } else {
            CP_WAIT0();
        }
        BARG(g);

        float sacc[32];
        #pragma unroll
        for (int i = 0; i < 32; i++) sacc[i] = 0.f;
        qk_one(sacc, sb + SM_QH, kst, wr0, n0);
        #pragma unroll
        for (int nb = 0; nb < 8; nb++) {
            rs0 += ex2f(sacc[nb*4+0] * cexp) + ex2f(sacc[nb*4+1] * cexp);
            rs1 += ex2f(sacc[nb*4+2] * cexp) + ex2f(sacc[nb*4+3] * cexp);
        }
        BARG(g);   // all group threads done with kst -> next copy may overwrite
    }

    // ---- row-sum reduce (intra-group) ----
    rs0 += __shfl_xor_sync(0xffffffff, rs0, 1);
    rs0 += __shfl_xor_sync(0xffffffff, rs0, 2);
    rs1 += __shfl_xor_sync(0xffffffff, rs1, 1);
    rs1 += __shfl_xor_sync(0xffffffff, rs1, 2);
    if ((lane & 3) == 0) {
        *(float*)(smem + SM_L + g * 512 + (nh * 64 + lwr0 + gr)     * 4) = rs0;
        *(float*)(smem + SM_L + g * 512 + (nh * 64 + lwr0 + 8 + gr) * 4) = rs1;
    }
    BARG(g);
    const float li0 = 1.0f / (*(float*)(smem + SM_L + g * 512 + (lwr0 + gr) * 4) +
                              *(float*)(smem + SM_L + g * 512 + (64 + lwr0 + gr) * 4));
    const float li1 = 1.0f / (*(float*)(smem + SM_L + g * 512 + (lwr0 + 8 + gr) * 4) +
                              *(float*)(smem + SM_L + g * 512 + (64 + lwr0 + 8 + gr) * 4));
    BARG(g);   // everyone read sums before stages reused

    float oacc[32];
    #pragma unroll
    for (int i = 0; i < 32; i++) oacc[i] = 0.f;

    // ================= pass 2: attention + O =================
    // prologue: K(0) -> Kst (32KB), V(0) -> Vst0 (32KB), one commit group
    gcopy(GB,         kbase, 32768, gtid);
    gcopy(GB + 32768, vbase, 32768, gtid);
    CP_COMMIT();

    for (int kt = 0; kt < NKT; kt++) {
        const uint32_t vst = GB + 32768 + (uint32_t)(kt & 1) * 32768;
        if (kt + 1 < NKT) {
            // V(t+1) into the other V stage (free since PV(t-1), BARG'd below)
            gcopy(GB + 32768 + (uint32_t)((kt + 1) & 1) * 32768,
                  vbase + (size_t)(kt + 1) * 32768, 32768, gtid);
            CP_COMMIT();
            CP_WAIT1();    // K(t), V(t) landed; V(t+1) pending
        } else {
            CP_WAIT0();
        }
        BARG(g);

        float sacc[32];
        #pragma unroll
        for (int i = 0; i < 32; i++) sacc[i] = 0.f;
        qk_three(sacc, sb + SM_QH, sb + SM_QL, GB, GB + 16384, wr0, n0);

        // exp, normalize, write attention, pack P into a-frags (hi/lo)
        uint32_t ph[16], pl[16];
        {
            float* arow0 = att + ((size_t)b * NN + q0 + wr0 + gr) * NN + kt * BN + n0 + c2;
            float* arow1 = arow0 + (size_t)8 * NN;
            #pragma unroll
            for (int nb = 0; nb < 8; nb++) {
                float p0 = ex2f(sacc[nb*4+0] * cexp) * li0;
                float p1 = ex2f(sacc[nb*4+1] * cexp) * li0;
                float p2 = ex2f(sacc[nb*4+2] * cexp) * li1;
                float p3 = ex2f(sacc[nb*4+3] * cexp) * li1;
                *(float2*)(arow0 + nb * 8) = make_float2(p0, p1);
                *(float2*)(arow1 + nb * 8) = make_float2(p2, p3);
                __nv_bfloat16 h0,h1,h2,h3,l0,l1,l2,l3;
                split1(p0,h0,l0); split1(p1,h1,l1); split1(p2,h2,l2); split1(p3,h3,l3);
                int ks = nb >> 1, hf2 = (nb & 1) * 2;
                ph[ks*4 + hf2 + 0] = bfpack(h0, h1);
                ph[ks*4 + hf2 + 1] = bfpack(h2, h3);
                pl[ks*4 + hf2 + 0] = bfpack(l0, l1);
                pl[ks*4 + hf2 + 1] = bfpack(l2, l3);
            }
        }
        BARG(g);   // all group threads done reading Kst
        if (kt + 1 < NKT) {
            gcopy(GB, kbase + (size_t)(kt + 1) * 32768, 32768, gtid);  // K(t+1) -> Kst
            CP_COMMIT();
        }

        // O += P V over this warp's k-half (3-product split)
        #pragma unroll
        for (int ks = 0; ks < 4; ks++) {
            const uint32_t* aH = ph + ks * 4;
            const uint32_t* aL = pl + ks * 4;
            const int k0 = n0 + ks * 16;
            #pragma unroll
            for (int db2 = 0; db2 < 4; db2++) {
                uint32_t bH[4], bL[4];
                ldb_v(bH, vst,         k0, db2 * 32);
                ldb_v(bL, vst + 16384, k0, db2 * 32);
                float* c0 = oacc + db2 * 8;
                mma16816(c0,     aH, bH);     mma16816(c0 + 4, aH, bH + 2);
                mma16816(c0,     aL, bH);     mma16816(c0 + 4, aL, bH + 2);
                mma16816(c0,     aH, bL);     mma16816(c0 + 4, aH, bL + 2);
            }
        }
        BARG(g);   // all done with V stage kt&1 before V(t+2) copy next iter
    }

    // ---- reduce O across the k-half warp pairs (intra-group), write context ----
    {
        char* red = smem + (GB - sb) + (size_t)((wid >> 1) & 3) * 4096;  // group V area, dead
        if (nh == 1) {
            #pragma unroll
            for (int db = 0; db < 8; db++) {
                *(float2*)(red + ((uint32_t)(gr)     * 64 + db * 8 + c2) * 4) =
                    make_float2(oacc[db*4+0], oacc[db*4+1]);
                *(float2*)(red + ((uint32_t)(gr + 8) * 64 + db * 8 + c2) * 4) =
                    make_float2(oacc[db*4+2], oacc[db*4+3]);
            }
        }
        BARG(g);
        if (nh == 0) {
            float* crow0 = ctx + ((size_t)b * NN + q0 + wr0 + gr) * DD + c2;
            float* crow1 = crow0 + 8 * DD;
            #pragma unroll
            for (int db = 0; db < 8; db++) {
                float2 a0 = *(float2*)(red + ((uint32_t)(gr)     * 64 + db * 8 + c2) * 4);
                float2 a1 = *(float2*)(red + ((uint32_t)(gr + 8) * 64 + db * 8 + c2) * 4);
                *(float2*)(crow0 + db * 8) = make_float2(oacc[db*4+0] + a0.x, oacc[db*4+1] + a0.y);
                *(float2*)(crow1 + db * 8) = make_float2(oacc[db*4+2] + a1.x, oacc[db*4+3] + a1.y);
            }
        }
    }
}

extern "C" void kernel_launch(void* const* d_in, const int* in_sizes, int n_in,
                              void* d_out, int out_size) {
    const float* q  = (const float*)d_in[0];
    const float* k  = (const float*)d_in[1];
    const float* v  = (const float*)d_in[2];
    const float* sc = (const float*)d_in[3];
    float* ctx = (float*)d_out;                          // [16,2048,64]
    float* att = (float*)d_out + (size_t)NB * NN * DD;   // [16,2048,2048]

    conv_kernel<<<dim3(NKT, NB, 3), 256>>>(q, k, v);

    cudaFuncSetAttribute(attn_kernel, cudaFuncAttributeMaxDynamicSharedMemorySize, SMEM_TOTAL);
    dim3 grid(NN / BM, NB);
    attn_kernel<<<grid, TB, SMEM_TOTAL>>>(sc, ctx, att);
}